// round 5
// baseline (speedup 1.0000x reference)
#include <cuda_runtime.h>
#include <cuda_bf16.h>
#include <math.h>

#define CD 128
#define NMAX 100352
#define EMAX 1700000

// ---------------- device scratch ----------------
__device__ __align__(16) float g_P[(size_t)NMAX * CD / 2];  // bf16 conv out (cast)
__device__ __align__(16) float g_H[(size_t)NMAX * CD / 2];  // bf16 hidden (cast)
__device__ float g_dis[NMAX];
__device__ int   g_cnt[NMAX];
__device__ int   g_off[NMAX];
__device__ int   g_cur[NMAX];
__device__ int   g_bkt[EMAX];
__device__ int   g_part[128];
__device__ __align__(16) __nv_bfloat16 g_Wb[3][CD * CD];  // bf16 W[c_out][c_in]

__device__ __forceinline__ unsigned int pack_bf16x2(float lo, float hi) {
    unsigned int r;
    asm("cvt.rn.bf16x2.f32 %0, %1, %2;" : "=r"(r) : "f"(hi), "f"(lo));
    return r;
}

// ---------------- small structural kernels ----------------
__global__ void k_zero_cnt(int n) {
    int i = blockIdx.x * blockDim.x + threadIdx.x;
    if (i < n) g_cnt[i] = 0;
}

__global__ void k_count(const int* __restrict__ col, int E) {
    for (int e = blockIdx.x * blockDim.x + threadIdx.x; e < E;
         e += gridDim.x * blockDim.x)
        atomicAdd(&g_cnt[col[e]], 1);
}

// scan + dis fused
__global__ void k_scan1(int n) {
    __shared__ int wsum[32];
    int tid = threadIdx.x;
    int lane = tid & 31, wid = tid >> 5;
    int i = blockIdx.x * 1024 + tid;
    int x = (i < n) ? g_cnt[i] : 0;
    if (i < n) g_dis[i] = rsqrtf((float)x + 1.0f);
    int v = x;
#pragma unroll
    for (int d = 1; d < 32; d <<= 1) {
        int t = __shfl_up_sync(0xFFFFFFFFu, v, d);
        if (lane >= d) v += t;
    }
    if (lane == 31) wsum[wid] = v;
    __syncthreads();
    if (wid == 0) {
        int w = wsum[lane];
#pragma unroll
        for (int d = 1; d < 32; d <<= 1) {
            int t = __shfl_up_sync(0xFFFFFFFFu, w, d);
            if (lane >= d) w += t;
        }
        wsum[lane] = w;
    }
    __syncthreads();
    int base = (wid > 0) ? wsum[wid - 1] : 0;
    if (i < n) g_off[i] = base + v - x;
    if (tid == 1023) g_part[blockIdx.x] = wsum[31];
}

__global__ void k_scan2(int nb) {
    __shared__ int s[128];
    int tid = threadIdx.x;
    int x = (tid < nb) ? g_part[tid] : 0;
    s[tid] = x;
    __syncthreads();
    for (int d = 1; d < 128; d <<= 1) {
        int t = (tid >= d) ? s[tid - d] : 0;
        __syncthreads();
        s[tid] += t;
        __syncthreads();
    }
    if (tid < nb) g_part[tid] = s[tid] - x;
}

__global__ void k_scan3(int n) {
    int i = blockIdx.x * blockDim.x + threadIdx.x;
    if (i < n) {
        int v = g_off[i] + g_part[i >> 10];
        g_off[i] = v;
        g_cur[i] = v;
    }
}

__global__ void k_fill(const int* __restrict__ row, const int* __restrict__ col, int E) {
    for (int e = blockIdx.x * blockDim.x + threadIdx.x; e < E;
         e += gridDim.x * blockDim.x) {
        int p = atomicAdd(&g_cur[col[e]], 1);
        g_bkt[p] = row[e];
    }
}

// convert all three weights at once: 3 * 16384 elements
__global__ void k_cvtW3(const float* __restrict__ W1, const float* __restrict__ W2,
                        const float* __restrict__ Wl) {
    int i = blockIdx.x * 256 + threadIdx.x;   // 192 blocks
    int which = i >> 14, j = i & 16383;
    const float* W = (which == 0) ? W1 : (which == 1) ? W2 : Wl;
    g_Wb[which][j] = __float2bfloat16(W[j]);
}

// ---------------- bf16 tensor-core GEMM (conv layers) -------------------------------
// P[i][c] = dis[i] * sum_k X[i][k] * W[c][k]; 128x128 tile, 256 thr, m16n8k16.
__global__ void __launch_bounds__(256)
k_gemm_bf16(const float* __restrict__ Xf, int useXf, int widx, int n) {
    __shared__ __align__(16) __nv_bfloat16 Xs[128][72];
    __shared__ __align__(16) __nv_bfloat16 Ws[128][72];

    const __nv_bfloat16* __restrict__ Hb = (const __nv_bfloat16*)g_H;
    const __nv_bfloat16* __restrict__ Wb = g_Wb[widx];

    int row0 = blockIdx.x * 128;
    int tid = threadIdx.x;
    int wid = tid >> 5, lane = tid & 31;
    int gid = lane >> 2, tig = lane & 3;
    int wm = wid >> 2, wn = wid & 3;
    int mbase = wm * 64, nbase = wn * 32;

    float acc[4][4][4];
#pragma unroll
    for (int a = 0; a < 4; a++)
#pragma unroll
        for (int b = 0; b < 4; b++)
#pragma unroll
            for (int c = 0; c < 4; c++) acc[a][b][c] = 0.0f;

    for (int kc = 0; kc < 128; kc += 64) {
        if (useXf) {
#pragma unroll
            for (int p = 0; p < 8; p++) {
                int f = tid + p * 256;
                int r = f >> 4, c4 = f & 15;
                float4 v = make_float4(0.f, 0.f, 0.f, 0.f);
                int gr = row0 + r;
                if (gr < n) v = *(const float4*)&Xf[(size_t)gr * CD + kc + c4 * 4];
                *(uint2*)&Xs[r][c4 * 4] =
                    make_uint2(pack_bf16x2(v.x, v.y), pack_bf16x2(v.z, v.w));
            }
        } else {
#pragma unroll
            for (int p = 0; p < 4; p++) {
                int f = tid + p * 256;
                int r = f >> 3, c8 = f & 7;
                uint4 v = make_uint4(0, 0, 0, 0);
                int gr = row0 + r;
                if (gr < n) v = *(const uint4*)&Hb[(size_t)gr * CD + kc + c8 * 8];
                *(uint4*)&Xs[r][c8 * 8] = v;
            }
        }
#pragma unroll
        for (int p = 0; p < 4; p++) {
            int f = tid + p * 256;
            int r = f >> 3, c8 = f & 7;
            *(uint4*)&Ws[r][c8 * 8] = *(const uint4*)&Wb[(size_t)r * CD + kc + c8 * 8];
        }
        __syncthreads();

#pragma unroll
        for (int kb = 0; kb < 64; kb += 16) {
            unsigned int af[4][4];
#pragma unroll
            for (int mt = 0; mt < 4; mt++) {
                int r = mbase + mt * 16 + gid;
                af[mt][0] = *(const unsigned int*)&Xs[r][kb + 2 * tig];
                af[mt][1] = *(const unsigned int*)&Xs[r + 8][kb + 2 * tig];
                af[mt][2] = *(const unsigned int*)&Xs[r][kb + 2 * tig + 8];
                af[mt][3] = *(const unsigned int*)&Xs[r + 8][kb + 2 * tig + 8];
            }
            unsigned int bfr[4][2];
#pragma unroll
            for (int nt = 0; nt < 4; nt++) {
                int cn = nbase + nt * 8 + gid;
                bfr[nt][0] = *(const unsigned int*)&Ws[cn][kb + 2 * tig];
                bfr[nt][1] = *(const unsigned int*)&Ws[cn][kb + 2 * tig + 8];
            }
#pragma unroll
            for (int mt = 0; mt < 4; mt++)
#pragma unroll
                for (int nt = 0; nt < 4; nt++) {
                    asm("mma.sync.aligned.m16n8k16.row.col.f32.bf16.bf16.f32 "
                        "{%0,%1,%2,%3}, {%4,%5,%6,%7}, {%8,%9}, {%0,%1,%2,%3};"
                        : "+f"(acc[mt][nt][0]), "+f"(acc[mt][nt][1]),
                          "+f"(acc[mt][nt][2]), "+f"(acc[mt][nt][3])
                        : "r"(af[mt][0]), "r"(af[mt][1]), "r"(af[mt][2]), "r"(af[mt][3]),
                          "r"(bfr[nt][0]), "r"(bfr[nt][1]));
                }
        }
        __syncthreads();
    }

    __nv_bfloat16* Pb = (__nv_bfloat16*)g_P;
#pragma unroll
    for (int mt = 0; mt < 4; mt++) {
        int r0 = row0 + mbase + mt * 16 + gid;
        int r1 = r0 + 8;
        float s0 = (r0 < n) ? g_dis[r0] : 0.0f;
        float s1 = (r1 < n) ? g_dis[r1] : 0.0f;
#pragma unroll
        for (int nt = 0; nt < 4; nt++) {
            int cn = nbase + nt * 8 + tig * 2;
            if (r0 < n)
                *(unsigned int*)&Pb[(size_t)r0 * CD + cn] =
                    pack_bf16x2(acc[mt][nt][0] * s0, acc[mt][nt][1] * s0);
            if (r1 < n)
                *(unsigned int*)&Pb[(size_t)r1 * CD + cn] =
                    pack_bf16x2(acc[mt][nt][2] * s1, acc[mt][nt][3] * s1);
        }
    }
}

// ---------------- GEMM + bias + log_softmax fused (final layer) ---------------------
__global__ void __launch_bounds__(256)
k_gemm_ls(const float* __restrict__ bl, float* __restrict__ out, int widx, int n) {
    __shared__ __align__(16) __nv_bfloat16 Xs[128][72];
    __shared__ __align__(16) __nv_bfloat16 Ws[128][72];
    __shared__ float smx[128][4];
    __shared__ float sms[128][4];

    const __nv_bfloat16* __restrict__ Hb = (const __nv_bfloat16*)g_H;
    const __nv_bfloat16* __restrict__ Wb = g_Wb[widx];

    int row0 = blockIdx.x * 128;
    int tid = threadIdx.x;
    int wid = tid >> 5, lane = tid & 31;
    int gid = lane >> 2, tig = lane & 3;
    int wm = wid >> 2, wn = wid & 3;
    int mbase = wm * 64, nbase = wn * 32;

    float acc[4][4][4];
#pragma unroll
    for (int a = 0; a < 4; a++)
#pragma unroll
        for (int b = 0; b < 4; b++)
#pragma unroll
            for (int c = 0; c < 4; c++) acc[a][b][c] = 0.0f;

    for (int kc = 0; kc < 128; kc += 64) {
#pragma unroll
        for (int p = 0; p < 4; p++) {
            int f = tid + p * 256;
            int r = f >> 3, c8 = f & 7;
            uint4 v = make_uint4(0, 0, 0, 0);
            int gr = row0 + r;
            if (gr < n) v = *(const uint4*)&Hb[(size_t)gr * CD + kc + c8 * 8];
            *(uint4*)&Xs[r][c8 * 8] = v;
        }
#pragma unroll
        for (int p = 0; p < 4; p++) {
            int f = tid + p * 256;
            int r = f >> 3, c8 = f & 7;
            *(uint4*)&Ws[r][c8 * 8] = *(const uint4*)&Wb[(size_t)r * CD + kc + c8 * 8];
        }
        __syncthreads();

#pragma unroll
        for (int kb = 0; kb < 64; kb += 16) {
            unsigned int af[4][4];
#pragma unroll
            for (int mt = 0; mt < 4; mt++) {
                int r = mbase + mt * 16 + gid;
                af[mt][0] = *(const unsigned int*)&Xs[r][kb + 2 * tig];
                af[mt][1] = *(const unsigned int*)&Xs[r + 8][kb + 2 * tig];
                af[mt][2] = *(const unsigned int*)&Xs[r][kb + 2 * tig + 8];
                af[mt][3] = *(const unsigned int*)&Xs[r + 8][kb + 2 * tig + 8];
            }
            unsigned int bfr[4][2];
#pragma unroll
            for (int nt = 0; nt < 4; nt++) {
                int cn = nbase + nt * 8 + gid;
                bfr[nt][0] = *(const unsigned int*)&Ws[cn][kb + 2 * tig];
                bfr[nt][1] = *(const unsigned int*)&Ws[cn][kb + 2 * tig + 8];
            }
#pragma unroll
            for (int mt = 0; mt < 4; mt++)
#pragma unroll
                for (int nt = 0; nt < 4; nt++) {
                    asm("mma.sync.aligned.m16n8k16.row.col.f32.bf16.bf16.f32 "
                        "{%0,%1,%2,%3}, {%4,%5,%6,%7}, {%8,%9}, {%0,%1,%2,%3};"
                        : "+f"(acc[mt][nt][0]), "+f"(acc[mt][nt][1]),
                          "+f"(acc[mt][nt][2]), "+f"(acc[mt][nt][3])
                        : "r"(af[mt][0]), "r"(af[mt][1]), "r"(af[mt][2]), "r"(af[mt][3]),
                          "r"(bfr[nt][0]), "r"(bfr[nt][1]));
                }
        }
        __syncthreads();
    }

    // add bias -> logits in acc
    float bv[4][2];
#pragma unroll
    for (int nt = 0; nt < 4; nt++) {
        int cn = nbase + nt * 8 + tig * 2;
        float2 b = *(const float2*)&bl[cn];
        bv[nt][0] = b.x; bv[nt][1] = b.y;
    }
#pragma unroll
    for (int mt = 0; mt < 4; mt++)
#pragma unroll
        for (int nt = 0; nt < 4; nt++) {
            acc[mt][nt][0] += bv[nt][0];
            acc[mt][nt][1] += bv[nt][1];
            acc[mt][nt][2] += bv[nt][0];
            acc[mt][nt][3] += bv[nt][1];
        }

    // pass 1: per-row max over this warp's 32 cols -> smx[row][wn]
#pragma unroll
    for (int mt = 0; mt < 4; mt++) {
        float m0 = -1e30f, m1 = -1e30f;
#pragma unroll
        for (int nt = 0; nt < 4; nt++) {
            m0 = fmaxf(m0, fmaxf(acc[mt][nt][0], acc[mt][nt][1]));
            m1 = fmaxf(m1, fmaxf(acc[mt][nt][2], acc[mt][nt][3]));
        }
        // reduce across the 4 lanes (tig) sharing this row
        m0 = fmaxf(m0, __shfl_xor_sync(0xFFFFFFFFu, m0, 1));
        m0 = fmaxf(m0, __shfl_xor_sync(0xFFFFFFFFu, m0, 2));
        m1 = fmaxf(m1, __shfl_xor_sync(0xFFFFFFFFu, m1, 1));
        m1 = fmaxf(m1, __shfl_xor_sync(0xFFFFFFFFu, m1, 2));
        if (tig == 0) {
            smx[mbase + mt * 16 + gid][wn] = m0;
            smx[mbase + mt * 16 + gid + 8][wn] = m1;
        }
    }
    __syncthreads();

    // pass 2: full max, then per-row sum(exp) partials
#pragma unroll
    for (int mt = 0; mt < 4; mt++) {
        int lr0 = mbase + mt * 16 + gid;
        int lr1 = lr0 + 8;
        float M0 = fmaxf(fmaxf(smx[lr0][0], smx[lr0][1]), fmaxf(smx[lr0][2], smx[lr0][3]));
        float M1 = fmaxf(fmaxf(smx[lr1][0], smx[lr1][1]), fmaxf(smx[lr1][2], smx[lr1][3]));
        float s0 = 0.0f, s1 = 0.0f;
#pragma unroll
        for (int nt = 0; nt < 4; nt++) {
            s0 += expf(acc[mt][nt][0] - M0) + expf(acc[mt][nt][1] - M0);
            s1 += expf(acc[mt][nt][2] - M1) + expf(acc[mt][nt][3] - M1);
        }
        s0 += __shfl_xor_sync(0xFFFFFFFFu, s0, 1);
        s0 += __shfl_xor_sync(0xFFFFFFFFu, s0, 2);
        s1 += __shfl_xor_sync(0xFFFFFFFFu, s1, 1);
        s1 += __shfl_xor_sync(0xFFFFFFFFu, s1, 2);
        if (tig == 0) {
            sms[lr0][wn] = s0;
            sms[lr1][wn] = s1;
        }
    }
    __syncthreads();

    // final: l = M + log(sum); write out = logit - l
#pragma unroll
    for (int mt = 0; mt < 4; mt++) {
        int lr0 = mbase + mt * 16 + gid;
        int lr1 = lr0 + 8;
        int r0 = row0 + lr0, r1 = row0 + lr1;
        float M0 = fmaxf(fmaxf(smx[lr0][0], smx[lr0][1]), fmaxf(smx[lr0][2], smx[lr0][3]));
        float M1 = fmaxf(fmaxf(smx[lr1][0], smx[lr1][1]), fmaxf(smx[lr1][2], smx[lr1][3]));
        float l0 = M0 + logf(sms[lr0][0] + sms[lr0][1] + sms[lr0][2] + sms[lr0][3]);
        float l1 = M1 + logf(sms[lr1][0] + sms[lr1][1] + sms[lr1][2] + sms[lr1][3]);
#pragma unroll
        for (int nt = 0; nt < 4; nt++) {
            int cn = nbase + nt * 8 + tig * 2;
            if (r0 < n)
                *(float2*)&out[(size_t)r0 * CD + cn] =
                    make_float2(acc[mt][nt][0] - l0, acc[mt][nt][1] - l0);
            if (r1 < n)
                *(float2*)&out[(size_t)r1 * CD + cn] =
                    make_float2(acc[mt][nt][2] - l1, acc[mt][nt][3] - l1);
        }
    }
}

// ---------------- gather (bf16 in, fp32 accum, bf16 out) ----------------------------
__global__ void k_gather(const float* __restrict__ bias, int n) {
    int w = (blockIdx.x * blockDim.x + threadIdx.x) >> 5;
    if (w >= n) return;
    int lane = threadIdx.x & 31;

    const uint2* __restrict__ P2 = (const uint2*)g_P;
    uint2 sv = P2[(size_t)w * 32 + lane];
    float ax = __low2float(*(__nv_bfloat162*)&sv.x);
    float ay = __high2float(*(__nv_bfloat162*)&sv.x);
    float az = __low2float(*(__nv_bfloat162*)&sv.y);
    float aw = __high2float(*(__nv_bfloat162*)&sv.y);

    int o = g_off[w];
    int c = g_cnt[w];
    int j = 0;
    for (; j + 4 <= c; j += 4) {
        int r0 = g_bkt[o + j];
        int r1 = g_bkt[o + j + 1];
        int r2 = g_bkt[o + j + 2];
        int r3 = g_bkt[o + j + 3];
        uint2 v0 = P2[(size_t)r0 * 32 + lane];
        uint2 v1 = P2[(size_t)r1 * 32 + lane];
        uint2 v2 = P2[(size_t)r2 * 32 + lane];
        uint2 v3 = P2[(size_t)r3 * 32 + lane];
        ax += __low2float(*(__nv_bfloat162*)&v0.x);
        ay += __high2float(*(__nv_bfloat162*)&v0.x);
        az += __low2float(*(__nv_bfloat162*)&v0.y);
        aw += __high2float(*(__nv_bfloat162*)&v0.y);
        ax += __low2float(*(__nv_bfloat162*)&v1.x);
        ay += __high2float(*(__nv_bfloat162*)&v1.x);
        az += __low2float(*(__nv_bfloat162*)&v1.y);
        aw += __high2float(*(__nv_bfloat162*)&v1.y);
        ax += __low2float(*(__nv_bfloat162*)&v2.x);
        ay += __high2float(*(__nv_bfloat162*)&v2.x);
        az += __low2float(*(__nv_bfloat162*)&v2.y);
        aw += __high2float(*(__nv_bfloat162*)&v2.y);
        ax += __low2float(*(__nv_bfloat162*)&v3.x);
        ay += __high2float(*(__nv_bfloat162*)&v3.x);
        az += __low2float(*(__nv_bfloat162*)&v3.y);
        aw += __high2float(*(__nv_bfloat162*)&v3.y);
    }
    for (; j < c; j++) {
        int r0 = g_bkt[o + j];
        uint2 v0 = P2[(size_t)r0 * 32 + lane];
        ax += __low2float(*(__nv_bfloat162*)&v0.x);
        ay += __high2float(*(__nv_bfloat162*)&v0.x);
        az += __low2float(*(__nv_bfloat162*)&v0.y);
        aw += __high2float(*(__nv_bfloat162*)&v0.y);
    }

    float s = g_dis[w];
    float4 b = *(const float4*)&bias[lane * 4];
    float ox = fmaxf(fmaf(ax, s, b.x), 0.0f);
    float oy = fmaxf(fmaf(ay, s, b.y), 0.0f);
    float oz = fmaxf(fmaf(az, s, b.z), 0.0f);
    float ow = fmaxf(fmaf(aw, s, b.w), 0.0f);
    ((uint2*)g_H)[(size_t)w * 32 + lane] =
        make_uint2(pack_bf16x2(ox, oy), pack_bf16x2(oz, ow));
}

// ---------------- launch ----------------
extern "C" void kernel_launch(void* const* d_in, const int* in_sizes, int n_in,
                              void* d_out, int out_size) {
    const float* x  = (const float*)d_in[0];
    const int*   ei = (const int*)d_in[1];
    const float* W1 = (const float*)d_in[2];
    const float* b1 = (const float*)d_in[3];
    const float* W2 = (const float*)d_in[4];
    const float* b2 = (const float*)d_in[5];
    const float* Wl = (const float*)d_in[6];
    const float* bl = (const float*)d_in[7];

    int n = in_sizes[0] / CD;
    int E = in_sizes[1] / 2;
    const int* row = ei;
    const int* col = ei + E;

    int nb256 = (n + 255) / 256;
    int nbScan = (n + 1023) / 1024;
    int gatherB = (n + 7) / 8;
    int gemmB = (n + 127) / 128;

    // weights (independent of everything else)
    k_cvtW3<<<192, 256>>>(W1, W2, Wl);

    // degree + bucketing
    k_zero_cnt<<<nb256, 256>>>(n);
    k_count<<<2048, 256>>>(col, E);
    k_scan1<<<nbScan, 1024>>>(n);
    k_scan2<<<1, 128>>>(nbScan);
    k_scan3<<<nb256, 256>>>(n);
    k_fill<<<2048, 256>>>(row, col, E);

    // conv1
    k_gemm_bf16<<<gemmB, 256>>>(x, 1, 0, n);
    k_gather<<<gatherB, 256>>>(b1, n);

    // conv2
    k_gemm_bf16<<<gemmB, 256>>>(nullptr, 0, 1, n);
    k_gather<<<gatherB, 256>>>(b2, n);

    // linear + log_softmax fused
    k_gemm_ls<<<gemmB, 256>>>(bl, (float*)d_out, 2, n);
}